// round 10
// baseline (speedup 1.0000x reference)
#include <cuda_runtime.h>

// Problem constants (z: [8192, 20, 256] f32, labels: [8192] i32, K=10)
#define NUM_LABELS 10
#define B_ROWS     8192
#define CH         5120          // C*H = 20*256
#define EPS        1e-8f

#define TPB            128       // threads per CTA in accumulate kernel
#define COLS_PER_CTA   512       // TPB * 4 (float4 per thread)
#define ROWS_PER_CHUNK 128
#define COL_BLOCKS     (CH / COLS_PER_CTA)          // 10
#define ROW_CHUNKS     (B_ROWS / ROWS_PER_CHUNK)    // 64

// Kernel-1 geometry: 40 zero CTAs + 4 independent scatter CTAs
#define K1_TPB       512
#define ZERO_CTAS    40          // 40*512 = 20480 threads >= 12800 float4 per array
#define SCATTER_CTAS 4           // CTAs 40..43, each scatters one quarter
#define QUARTER      (B_ROWS / SCATTER_CTAS)        // 2048 labels
#define QUARTER4     (QUARTER / 4)                  // 512 int4

// Scratch (allocation-free: __device__ globals)
__device__ __align__(16) float g_sum [NUM_LABELS * CH];
__device__ __align__(16) float g_sum2[NUM_LABELS * CH];
__device__ int g_rl[B_ROWS];        // (row << 4) | label, grouped by label
__device__ int g_counts[NUM_LABELS];

// ---------------------------------------------------------------------------
// Kernel 1: zero (CTAs 0..39) | independent scatter CTAs (40..43).
// Each scatter CTA redundantly histograms ALL quarters (32 KB of labels,
// L2-resident), derives its own global bases, and scatters its quarter.
// Triggers PDL completion after its last dependent-visible write.
// ---------------------------------------------------------------------------
__global__ __launch_bounds__(K1_TPB) void prep_kernel(const int* __restrict__ labels,
                                                      float* __restrict__ out) {
    const int tid = threadIdx.x;

    if (blockIdx.x < ZERO_CTAS) {
        int i = blockIdx.x * K1_TPB + tid;                  // float4 index
        const int n4 = (NUM_LABELS * CH) / 4;               // 12800
        float4 zv = make_float4(0.f, 0.f, 0.f, 0.f);
        if (i < n4) {
            ((float4*)g_sum)[i]  = zv;
            ((float4*)g_sum2)[i] = zv;
        }
        if (i == 0) out[0] = 0.0f;
        __threadfence();
        cudaTriggerProgrammaticLaunchCompletion();
        return;
    }

    // ---- scatter CTA c (c = 0..3): full histogram + scatter quarter c ----
    __shared__ int bins[16][NUM_LABELS];     // per-warp bins; warp w counts quarter w/4
    __shared__ int hist_q[SCATTER_CTAS][NUM_LABELS];
    __shared__ int cursor[NUM_LABELS];       // scatter cursors for my quarter

    const int c    = blockIdx.x - ZERO_CTAS;
    const int wid  = tid >> 5;
    const int lane = tid & 31;
    const int4* __restrict__ lab4 = (const int4*)labels;

    if (tid < 16 * NUM_LABELS) ((int*)bins)[tid] = 0;
    __syncthreads();

    // Warps [4q, 4q+4) histogram quarter q: 512 int4 over 128 threads -> 4 each
    {
        const int q    = wid >> 2;                      // quarter this warp counts
        const int t128 = (wid & 3) * 32 + lane;         // 0..127 within quarter team
        #pragma unroll
        for (int it = 0; it < QUARTER4 / 128; it++) {   // 4 iterations
            int4 v = lab4[q * QUARTER4 + it * 128 + t128];
            atomicAdd(&bins[wid][v.x], 1);
            atomicAdd(&bins[wid][v.y], 1);
            atomicAdd(&bins[wid][v.z], 1);
            atomicAdd(&bins[wid][v.w], 1);
        }
    }
    __syncthreads();

    // Reduce per-warp bins into per-quarter histograms
    if (tid < SCATTER_CTAS * NUM_LABELS) {
        int q = tid / NUM_LABELS, k = tid % NUM_LABELS;
        hist_q[q][k] = bins[4*q+0][k] + bins[4*q+1][k] + bins[4*q+2][k] + bins[4*q+3][k];
    }
    __syncthreads();

    // Global prefix + my quarter's starting base per label
    if (tid == 0) {
        int total[NUM_LABELS];
        #pragma unroll
        for (int k = 0; k < NUM_LABELS; k++)
            total[k] = hist_q[0][k] + hist_q[1][k] + hist_q[2][k] + hist_q[3][k];
        int acc = 0;
        #pragma unroll
        for (int k = 0; k < NUM_LABELS; k++) {
            int base = acc;                              // global start of label k
            for (int q = 0; q < c; q++) base += hist_q[q][k];
            cursor[k] = base;
            acc += total[k];
        }
        if (c == 0) {
            #pragma unroll
            for (int k = 0; k < NUM_LABELS; k++) g_counts[k] = total[k];
        }
    }
    __syncthreads();

    // Scatter my quarter: 512 threads x 1 int4, warp-aggregated smem atomics
    {
        int i4 = c * QUARTER4 + tid;
        int4 v = lab4[i4];
        int b0 = i4 * 4;
        #pragma unroll
        for (int j = 0; j < 4; j++) {
            int lab = (j == 0) ? v.x : (j == 1) ? v.y : (j == 2) ? v.z : v.w;
            unsigned mask = __match_any_sync(0xffffffffu, lab);
            int leader = __ffs(mask) - 1;
            int rank   = __popc(mask & ((1u << lane) - 1u));
            int base = 0;
            if (lane == leader) base = atomicAdd(&cursor[lab], __popc(mask));
            base = __shfl_sync(0xffffffffu, base, leader);
            g_rl[base + rank] = ((b0 + j) << 4) | lab;
        }
    }
    __threadfence();
    cudaTriggerProgrammaticLaunchCompletion();
}

// ---------------------------------------------------------------------------
// Kernel 2: one-pass segmented sum / sum-of-squares (pristine R2/R4 body).
// grid = (COL_BLOCKS, ROW_CHUNKS), 128 threads, float4/thread, MLP=8.
// PDL: gridsync before consuming g_rl; trigger after final flush.
// ---------------------------------------------------------------------------
__device__ __forceinline__ void flush_acc(int lab, int colBase,
                                          float4& a, float4& a2) {
    int base = lab * CH + colBase;
    atomicAdd(&g_sum [base + 0], a.x);
    atomicAdd(&g_sum [base + 1], a.y);
    atomicAdd(&g_sum [base + 2], a.z);
    atomicAdd(&g_sum [base + 3], a.w);
    atomicAdd(&g_sum2[base + 0], a2.x);
    atomicAdd(&g_sum2[base + 1], a2.y);
    atomicAdd(&g_sum2[base + 2], a2.z);
    atomicAdd(&g_sum2[base + 3], a2.w);
    a  = make_float4(0.f, 0.f, 0.f, 0.f);
    a2 = make_float4(0.f, 0.f, 0.f, 0.f);
}

__global__ __launch_bounds__(TPB) void accum_kernel(const float* __restrict__ z) {
    __shared__ int s_rl[ROWS_PER_CHUNK];
    const int tid = threadIdx.x;
    const int cb  = blockIdx.x;   // column block 0..9
    const int rc  = blockIdx.y;   // row chunk   0..63

    cudaGridDependencySynchronize();       // wait for prep's g_rl / zeroed sums

    s_rl[tid] = g_rl[rc * ROWS_PER_CHUNK + tid];
    __syncthreads();

    const float4* __restrict__ z4 = (const float4*)z;
    const int col4    = cb * (COLS_PER_CTA / 4) + tid;   // float4 index in row
    const int colBase = cb * COLS_PER_CTA + tid * 4;     // scalar column base

    float4 a  = make_float4(0.f, 0.f, 0.f, 0.f);
    float4 a2 = make_float4(0.f, 0.f, 0.f, 0.f);
    int cur = s_rl[0] & 15;

    for (int i = 0; i < ROWS_PER_CHUNK; i += 8) {
        int    rl[8];
        float4 v[8];
        #pragma unroll
        for (int u = 0; u < 8; u++) rl[u] = s_rl[i + u];
        #pragma unroll
        for (int u = 0; u < 8; u++) v[u] = z4[(rl[u] >> 4) * (CH / 4) + col4];

        #pragma unroll
        for (int u = 0; u < 8; u++) {
            int lab = rl[u] & 15;
            if (lab != cur) { flush_acc(cur, colBase, a, a2); cur = lab; }
            a.x += v[u].x; a.y += v[u].y; a.z += v[u].z; a.w += v[u].w;
            a2.x = fmaf(v[u].x, v[u].x, a2.x);
            a2.y = fmaf(v[u].y, v[u].y, a2.y);
            a2.z = fmaf(v[u].z, v[u].z, a2.z);
            a2.w = fmaf(v[u].w, v[u].w, a2.w);
        }
    }
    flush_acc(cur, colBase, a, a2);

    __threadfence();
    cudaTriggerProgrammaticLaunchCompletion();
}

// ---------------------------------------------------------------------------
// Kernel 3: finalize.  grid = (NUM_LABELS, CH/1024), 1024 thr, 1 cell/thread.
// sse(k,j) = q - 2*m'*s + n*m'^2, m' = s/n - EPS; CTA-reduce; atomicAdd.
// PDL: gridsync before reading g_sum/g_sum2. (out[0] zeroed by prep.)
// ---------------------------------------------------------------------------
__global__ __launch_bounds__(1024) void finalize_kernel(float* __restrict__ out) {
    __shared__ float sh[32];
    const int k   = blockIdx.x;
    const int j   = blockIdx.y * 1024 + threadIdx.x;
    const int tid = threadIdx.x;

    cudaGridDependencySynchronize();       // wait for accum's atomics

    float n = (float)g_counts[k];
    float acc = 0.0f;
    if (n > 0.0f) {
        int idx  = k * CH + j;
        float s  = g_sum[idx];
        float q  = g_sum2[idx];
        float mp = s / n - EPS;
        float e  = q - 2.0f * mp * s + n * mp * mp;
        acc = e / (n * (float)CH);
    }
    #pragma unroll
    for (int o = 16; o > 0; o >>= 1) acc += __shfl_down_sync(0xffffffffu, acc, o);
    if ((tid & 31) == 0) sh[tid >> 5] = acc;
    __syncthreads();
    if (tid < 32) {
        float v = sh[tid];
        #pragma unroll
        for (int o = 16; o > 0; o >>= 1) v += __shfl_down_sync(0xffffffffu, v, o);
        if (tid == 0) atomicAdd(out, v);
    }
}

// ---------------------------------------------------------------------------
extern "C" void kernel_launch(void* const* d_in, const int* in_sizes, int n_in,
                              void* d_out, int out_size) {
    const float* z      = (const float*)d_in[0];
    const int*   labels = (const int*)d_in[1];
    (void)in_sizes; (void)n_in; (void)out_size;

    // prep: normal launch
    prep_kernel<<<ZERO_CTAS + SCATTER_CTAS, K1_TPB>>>(labels, (float*)d_out);

    // accum + finalize: PDL (programmatic stream serialization) so the grid
    // is pre-staged and launches as the predecessor drains.
    cudaLaunchAttribute attr[1];
    attr[0].id = cudaLaunchAttributeProgrammaticStreamSerialization;
    attr[0].val.programmaticStreamSerializationAllowed = 1;

    {
        cudaLaunchConfig_t cfg = {};
        cfg.gridDim  = dim3(COL_BLOCKS, ROW_CHUNKS);
        cfg.blockDim = dim3(TPB);
        cfg.dynamicSmemBytes = 0;
        cfg.stream = 0;
        cfg.attrs = attr;
        cfg.numAttrs = 1;
        cudaLaunchKernelEx(&cfg, accum_kernel, z);
    }
    {
        cudaLaunchConfig_t cfg = {};
        cfg.gridDim  = dim3(NUM_LABELS, CH / 1024);
        cfg.blockDim = dim3(1024);
        cfg.dynamicSmemBytes = 0;
        cfg.stream = 0;
        cfg.attrs = attr;
        cfg.numAttrs = 1;
        cudaLaunchKernelEx(&cfg, finalize_kernel, (float*)d_out);
    }
}

// round 11
// speedup vs baseline: 1.1662x; 1.1662x over previous
#include <cuda_runtime.h>

// Problem constants (z: [8192, 20, 256] f32, labels: [8192] i32, K=10)
#define NUM_LABELS 10
#define B_ROWS     8192
#define CH         5120          // C*H = 20*256
#define EPS        1e-8f

#define TPB            128       // threads per CTA in accumulate kernel
#define COLS_PER_CTA   512       // TPB * 4 (float4 per thread)
#define ROWS_PER_CHUNK 128
#define COL_BLOCKS     (CH / COLS_PER_CTA)          // 10
#define ROW_CHUNKS     (B_ROWS / ROWS_PER_CHUNK)    // 64

// Kernel-1 geometry: 4 independent scatter CTAs (no zero CTAs needed —
// finalize restores g_sum/g_sum2 to zero after reading them).
#define K1_TPB       512
#define SCATTER_CTAS 4           // each scatters one quarter of the labels
#define QUARTER      (B_ROWS / SCATTER_CTAS)        // 2048 labels
#define QUARTER4     (QUARTER / 4)                  // 512 int4

// Scratch (allocation-free: __device__ globals).
// INVARIANT: g_sum / g_sum2 are all-zero at kernel_launch entry.
//   - initially: zero-initialized at module load
//   - thereafter: finalize_kernel stores 0 back after consuming each cell
__device__ __align__(16) float g_sum [NUM_LABELS * CH];
__device__ __align__(16) float g_sum2[NUM_LABELS * CH];
__device__ int g_rl[B_ROWS];        // (row << 4) | label, grouped by label
__device__ int g_counts[NUM_LABELS];

// ---------------------------------------------------------------------------
// Kernel 1: 4 independent scatter CTAs. Each redundantly histograms ALL
// quarters (32 KB of labels, L2-resident), derives its own global bases,
// and scatters its quarter. No inter-CTA communication.
// ---------------------------------------------------------------------------
__global__ __launch_bounds__(K1_TPB) void prep_kernel(const int* __restrict__ labels,
                                                      float* __restrict__ out) {
    __shared__ int bins[16][NUM_LABELS];     // per-warp bins; warp w counts quarter w/4
    __shared__ int hist_q[SCATTER_CTAS][NUM_LABELS];
    __shared__ int cursor[NUM_LABELS];       // scatter cursors for my quarter

    const int tid  = threadIdx.x;
    const int c    = blockIdx.x;             // 0..3
    const int wid  = tid >> 5;
    const int lane = tid & 31;
    const int4* __restrict__ lab4 = (const int4*)labels;

    if (c == 0 && tid == 0) out[0] = 0.0f;

    if (tid < 16 * NUM_LABELS) ((int*)bins)[tid] = 0;
    __syncthreads();

    // Warps [4q, 4q+4) histogram quarter q: 512 int4 over 128 threads -> 4 each
    {
        const int q    = wid >> 2;                      // quarter this warp counts
        const int t128 = (wid & 3) * 32 + lane;         // 0..127 within quarter team
        #pragma unroll
        for (int it = 0; it < QUARTER4 / 128; it++) {   // 4 iterations
            int4 v = lab4[q * QUARTER4 + it * 128 + t128];
            atomicAdd(&bins[wid][v.x], 1);
            atomicAdd(&bins[wid][v.y], 1);
            atomicAdd(&bins[wid][v.z], 1);
            atomicAdd(&bins[wid][v.w], 1);
        }
    }
    __syncthreads();

    // Reduce per-warp bins into per-quarter histograms
    if (tid < SCATTER_CTAS * NUM_LABELS) {
        int q = tid / NUM_LABELS, k = tid % NUM_LABELS;
        hist_q[q][k] = bins[4*q+0][k] + bins[4*q+1][k] + bins[4*q+2][k] + bins[4*q+3][k];
    }
    __syncthreads();

    // Global prefix + my quarter's starting base per label
    if (tid == 0) {
        int total[NUM_LABELS];
        #pragma unroll
        for (int k = 0; k < NUM_LABELS; k++)
            total[k] = hist_q[0][k] + hist_q[1][k] + hist_q[2][k] + hist_q[3][k];
        int acc = 0;
        #pragma unroll
        for (int k = 0; k < NUM_LABELS; k++) {
            int base = acc;                              // global start of label k
            for (int q = 0; q < c; q++) base += hist_q[q][k];
            cursor[k] = base;
            acc += total[k];
        }
        if (c == 0) {
            #pragma unroll
            for (int k = 0; k < NUM_LABELS; k++) g_counts[k] = total[k];
        }
    }
    __syncthreads();

    // Scatter my quarter: 512 threads x 1 int4, warp-aggregated smem atomics
    {
        int i4 = c * QUARTER4 + tid;
        int4 v = lab4[i4];
        int b0 = i4 * 4;
        #pragma unroll
        for (int j = 0; j < 4; j++) {
            int lab = (j == 0) ? v.x : (j == 1) ? v.y : (j == 2) ? v.z : v.w;
            unsigned mask = __match_any_sync(0xffffffffu, lab);
            int leader = __ffs(mask) - 1;
            int rank   = __popc(mask & ((1u << lane) - 1u));
            int base = 0;
            if (lane == leader) base = atomicAdd(&cursor[lab], __popc(mask));
            base = __shfl_sync(0xffffffffu, base, leader);
            g_rl[base + rank] = ((b0 + j) << 4) | lab;
        }
    }
}

// ---------------------------------------------------------------------------
// Kernel 2: one-pass segmented sum / sum-of-squares (pristine R2/R4 body).
// grid = (COL_BLOCKS, ROW_CHUNKS), 128 threads, float4/thread, MLP=8.
// Rows walked in globally label-grouped order -> ~2 flushes per CTA.
// ---------------------------------------------------------------------------
__device__ __forceinline__ void flush_acc(int lab, int colBase,
                                          float4& a, float4& a2) {
    int base = lab * CH + colBase;
    atomicAdd(&g_sum [base + 0], a.x);
    atomicAdd(&g_sum [base + 1], a.y);
    atomicAdd(&g_sum [base + 2], a.z);
    atomicAdd(&g_sum [base + 3], a.w);
    atomicAdd(&g_sum2[base + 0], a2.x);
    atomicAdd(&g_sum2[base + 1], a2.y);
    atomicAdd(&g_sum2[base + 2], a2.z);
    atomicAdd(&g_sum2[base + 3], a2.w);
    a  = make_float4(0.f, 0.f, 0.f, 0.f);
    a2 = make_float4(0.f, 0.f, 0.f, 0.f);
}

__global__ __launch_bounds__(TPB) void accum_kernel(const float* __restrict__ z) {
    __shared__ int s_rl[ROWS_PER_CHUNK];
    const int tid = threadIdx.x;
    const int cb  = blockIdx.x;   // column block 0..9
    const int rc  = blockIdx.y;   // row chunk   0..63

    s_rl[tid] = g_rl[rc * ROWS_PER_CHUNK + tid];
    __syncthreads();

    const float4* __restrict__ z4 = (const float4*)z;
    const int col4    = cb * (COLS_PER_CTA / 4) + tid;   // float4 index in row
    const int colBase = cb * COLS_PER_CTA + tid * 4;     // scalar column base

    float4 a  = make_float4(0.f, 0.f, 0.f, 0.f);
    float4 a2 = make_float4(0.f, 0.f, 0.f, 0.f);
    int cur = s_rl[0] & 15;

    for (int i = 0; i < ROWS_PER_CHUNK; i += 8) {
        int    rl[8];
        float4 v[8];
        #pragma unroll
        for (int u = 0; u < 8; u++) rl[u] = s_rl[i + u];
        #pragma unroll
        for (int u = 0; u < 8; u++) v[u] = z4[(rl[u] >> 4) * (CH / 4) + col4];

        #pragma unroll
        for (int u = 0; u < 8; u++) {
            int lab = rl[u] & 15;
            if (lab != cur) { flush_acc(cur, colBase, a, a2); cur = lab; }
            a.x += v[u].x; a.y += v[u].y; a.z += v[u].z; a.w += v[u].w;
            a2.x = fmaf(v[u].x, v[u].x, a2.x);
            a2.y = fmaf(v[u].y, v[u].y, a2.y);
            a2.z = fmaf(v[u].z, v[u].z, a2.z);
            a2.w = fmaf(v[u].w, v[u].w, a2.w);
        }
    }
    flush_acc(cur, colBase, a, a2);
}

// ---------------------------------------------------------------------------
// Kernel 3: finalize.  grid = (NUM_LABELS, CH/1024), 1024 thr, 1 cell/thread.
// sse(k,j) = q - 2*m'*s + n*m'^2, m' = s/n - EPS; CTA-reduce; atomicAdd.
// Each cell is read exactly once -> store 0 back to restore the all-zero
// invariant for the next replay (removes the zeroing pass entirely).
// ---------------------------------------------------------------------------
__global__ __launch_bounds__(1024) void finalize_kernel(float* __restrict__ out) {
    __shared__ float sh[32];
    const int k   = blockIdx.x;
    const int j   = blockIdx.y * 1024 + threadIdx.x;
    const int tid = threadIdx.x;

    const int idx = k * CH + j;
    float n = (float)g_counts[k];
    float s = g_sum[idx];
    float q = g_sum2[idx];
    g_sum[idx]  = 0.0f;                    // restore invariant for next replay
    g_sum2[idx] = 0.0f;

    float acc = 0.0f;
    if (n > 0.0f) {
        float mp = s / n - EPS;
        float e  = q - 2.0f * mp * s + n * mp * mp;
        acc = e / (n * (float)CH);
    }
    #pragma unroll
    for (int o = 16; o > 0; o >>= 1) acc += __shfl_down_sync(0xffffffffu, acc, o);
    if ((tid & 31) == 0) sh[tid >> 5] = acc;
    __syncthreads();
    if (tid < 32) {
        float v = sh[tid];
        #pragma unroll
        for (int o = 16; o > 0; o >>= 1) v += __shfl_down_sync(0xffffffffu, v, o);
        if (tid == 0) atomicAdd(out, v);
    }
}

// ---------------------------------------------------------------------------
extern "C" void kernel_launch(void* const* d_in, const int* in_sizes, int n_in,
                              void* d_out, int out_size) {
    const float* z      = (const float*)d_in[0];
    const int*   labels = (const int*)d_in[1];
    (void)in_sizes; (void)n_in; (void)out_size;

    prep_kernel<<<SCATTER_CTAS, K1_TPB>>>(labels, (float*)d_out);
    accum_kernel<<<dim3(COL_BLOCKS, ROW_CHUNKS), TPB>>>(z);
    finalize_kernel<<<dim3(NUM_LABELS, CH / 1024), 1024>>>((float*)d_out);
}